// round 1
// baseline (speedup 1.0000x reference)
#include <cuda_runtime.h>
#include <math.h>

#define Bb 32
#define Tt 512
#define Dd 512
#define Hh 2048
#define H3 6144
#define Pp 1024
#define MT (Bb*Tt)   // 16384

// ---------------- scratch (device globals; no allocation allowed) ----------------
__device__ float g_A1[MT * 1024];          //  64 MB  relu(x@W1^T+b1)
__device__ float g_A2[MT * Hh];            // 128 MB  relu(.@W2^T+b2)
__device__ float g_GI[MT * H3];            // 384 MB  gi, stored (T,B,3H)
__device__ float g_HS[MT * Hh];            // 128 MB  h_t history, stored (T,B,H)
__device__ float g_S [MT * Pp];            //  64 MB  relu(h@W3^T+b3), rows (t*B+b)

// ---------------- generic TN SGEMM: C = act(A[M,K] @ B[N,K]^T + bias) ------------
#define BM 128
#define BN 128
#define BK 8
#define TM 8
#define TN 8

__global__ __launch_bounds__(256)
void sgemm_tn(const float* __restrict__ A, const float* __restrict__ B,
              const float* __restrict__ bias, float* __restrict__ C,
              int M, int N, int K, int doRelu, int permute)
{
    __shared__ float As[BK][BM];
    __shared__ float Bs[BK][BN];
    const int tid = threadIdx.x;
    const int tx  = tid & 15;      // N direction
    const int ty  = tid >> 4;      // M direction
    const int lr  = tid >> 1;      // load row 0..127
    const int lk  = (tid & 1) * 4; // 0 or 4

    const float* Ap = A + (size_t)(blockIdx.y * BM + lr) * K + lk;
    const float* Bp = B + (size_t)(blockIdx.x * BN + lr) * K + lk;

    float acc[TM][TN];
#pragma unroll
    for (int i = 0; i < TM; i++)
#pragma unroll
        for (int j = 0; j < TN; j++) acc[i][j] = 0.f;

    for (int k0 = 0; k0 < K; k0 += BK) {
        float4 av = *(const float4*)(Ap + k0);
        float4 bv = *(const float4*)(Bp + k0);
        As[lk + 0][lr] = av.x; As[lk + 1][lr] = av.y;
        As[lk + 2][lr] = av.z; As[lk + 3][lr] = av.w;
        Bs[lk + 0][lr] = bv.x; Bs[lk + 1][lr] = bv.y;
        Bs[lk + 2][lr] = bv.z; Bs[lk + 3][lr] = bv.w;
        __syncthreads();
#pragma unroll
        for (int k = 0; k < BK; k++) {
            float ar[TM], br[TN];
#pragma unroll
            for (int i = 0; i < TM; i++) ar[i] = As[k][ty * TM + i];
#pragma unroll
            for (int j = 0; j < TN; j++) br[j] = Bs[k][tx * TN + j];
#pragma unroll
            for (int i = 0; i < TM; i++)
#pragma unroll
                for (int j = 0; j < TN; j++)
                    acc[i][j] = fmaf(ar[i], br[j], acc[i][j]);
        }
        __syncthreads();
    }

#pragma unroll
    for (int i = 0; i < TM; i++) {
        int r = blockIdx.y * BM + ty * TM + i;         // r = b*T + t
        int outr = permute ? ((r & (Tt - 1)) * Bb + (r >> 9)) : r;  // -> t*B + b
        float* Cp = C + (size_t)outr * N + blockIdx.x * BN + tx * TN;
        int colb = blockIdx.x * BN + tx * TN;
#pragma unroll
        for (int j = 0; j < TN; j++) {
            float v = acc[i][j] + bias[colb + j];
            if (doRelu) v = fmaxf(v, 0.f);
            Cp[j] = v;
        }
    }
}

// ---------------- fused GRU step: gh = h@W_hh^T + b_hh, gates, h update ----------
// Block: 16 h-columns x all 32 batch rows (M=32, N=48 incl. 3 gates, K=2048).
#define GNT 16
#define GKT 32

__global__ __launch_bounds__(256)
void gru_step(const float* __restrict__ gi_t,   // (B, 3H) for this t
              const float* __restrict__ hprev,  // (B, H)
              const float* __restrict__ Whh,    // (3H, H)
              const float* __restrict__ bhh,    // (3H)
              float* __restrict__ hnew)         // (B, H)
{
    __shared__ float sh[32][GKT + 1];
    __shared__ float sw[48][GKT + 1];
    const int tid  = threadIdx.x;
    const int base = blockIdx.x * GNT;
    const int b    = tid >> 3;   // 0..31
    const int sub  = tid & 7;    // 0..7

    float acc[6] = {0.f, 0.f, 0.f, 0.f, 0.f, 0.f};  // cols sub+8j, j=0..5

    for (int k0 = 0; k0 < Hh; k0 += GKT) {
#pragma unroll
        for (int i = tid; i < 32 * GKT; i += 256)
            sh[i >> 5][i & 31] = hprev[(size_t)(i >> 5) * Hh + k0 + (i & 31)];
#pragma unroll
        for (int i = tid; i < 48 * GKT; i += 256) {
            int r = i >> 5, c = i & 31;
            sw[r][c] = Whh[(size_t)((r >> 4) * Hh + base + (r & 15)) * Hh + k0 + c];
        }
        __syncthreads();
#pragma unroll
        for (int k = 0; k < GKT; k++) {
            float hv = sh[b][k];
#pragma unroll
            for (int j = 0; j < 6; j++)
                acc[j] = fmaf(hv, sw[sub + 8 * j][k], acc[j]);
        }
        __syncthreads();
    }

    // col = sub + 8j: j=0,1 -> gate r; j=2,3 -> gate z; j=4,5 -> gate n
    const float* gib = gi_t + (size_t)b * H3;
#pragma unroll
    for (int p = 0; p < 2; p++) {
        int col = base + sub + 8 * p;
        float ghr = acc[0 + p] + bhh[col];
        float ghz = acc[2 + p] + bhh[Hh + col];
        float ghn = acc[4 + p] + bhh[2 * Hh + col];
        float rr  = 1.f / (1.f + expf(-(gib[col]          + ghr)));
        float zz  = 1.f / (1.f + expf(-(gib[Hh + col]     + ghz)));
        float nn  = tanhf(gib[2 * Hh + col] + rr * ghn);
        float hp  = hprev[(size_t)b * Hh + col];
        hnew[(size_t)b * Hh + col] = (1.f - zz) * nn + zz * hp;
    }
}

// ---------------- head: out[b,t,j] = S[t*B+b,:] . Wp[j,label[b],:] + bp ----------
__global__ __launch_bounds__(256)
void head_kernel(const float* __restrict__ S, const float* __restrict__ Wp,
                 const float* __restrict__ bp, const int* __restrict__ label,
                 float* __restrict__ out)
{
    int w    = blockIdx.x * 8 + (threadIdx.x >> 5);  // 0..49151
    int lane = threadIdx.x & 31;
    int bt = w / 3, j = w % 3;
    int t = bt >> 5, b = bt & 31;                    // S row = t*32 + b
    int lab = label[b];
    const float* sp = S  + (size_t)bt * Pp;
    const float* wp = Wp + (size_t)(j * 8 + lab) * Pp;
    float sum = 0.f;
    for (int d = lane; d < Pp; d += 32)
        sum = fmaf(sp[d], wp[d], sum);
#pragma unroll
    for (int o = 16; o > 0; o >>= 1) sum += __shfl_xor_sync(0xffffffffu, sum, o);
    if (lane == 0)
        out[(size_t)b * Tt * 3 + t * 3 + j] = sum + bp[j * 8 + lab];
}

__global__ void copy_hlast(const float* __restrict__ src, float* __restrict__ dst)
{
    int i = blockIdx.x * 256 + threadIdx.x;
    if (i < Bb * Hh) dst[i] = src[i];
}

// ---------------- launch ---------------------------------------------------------
extern "C" void kernel_launch(void* const* d_in, const int* in_sizes, int n_in,
                              void* d_out, int out_size)
{
    (void)in_sizes; (void)n_in; (void)out_size;
    const float* x     = (const float*)d_in[0];
    const int*   label = (const int*)  d_in[1];
    const float* h0    = (const float*)d_in[2];
    const float* W1  = (const float*)d_in[3];  const float* b1  = (const float*)d_in[4];
    const float* W2  = (const float*)d_in[5];  const float* b2  = (const float*)d_in[6];
    const float* Wih = (const float*)d_in[7];  const float* bih = (const float*)d_in[8];
    const float* Whh = (const float*)d_in[9];  const float* bhh = (const float*)d_in[10];
    const float* W3  = (const float*)d_in[11]; const float* b3  = (const float*)d_in[12];
    const float* Wp  = (const float*)d_in[13]; const float* bp  = (const float*)d_in[14];
    float* out = (float*)d_out;

    float *A1, *A2, *GI, *HS, *S;
    cudaGetSymbolAddress((void**)&A1, g_A1);
    cudaGetSymbolAddress((void**)&A2, g_A2);
    cudaGetSymbolAddress((void**)&GI, g_GI);
    cudaGetSymbolAddress((void**)&HS, g_HS);
    cudaGetSymbolAddress((void**)&S,  g_S);

    // MLP front-end
    sgemm_tn<<<dim3(1024 / BN, MT / BM), 256>>>(x,  W1, b1, A1, MT, 1024, Dd, 1, 0);
    sgemm_tn<<<dim3(Hh   / BN, MT / BM), 256>>>(A1, W2, b2, A2, MT, Hh, 1024, 1, 0);
    // gi = A2 @ W_ih^T + b_ih, written permuted to (T, B, 3H)
    sgemm_tn<<<dim3(H3   / BN, MT / BM), 256>>>(A2, Wih, bih, GI, MT, H3, Hh, 0, 1);

    // GRU scan (sequential over T)
    for (int t = 0; t < Tt; t++) {
        const float* hp = (t == 0) ? h0 : (HS + (size_t)(t - 1) * Bb * Hh);
        gru_step<<<Hh / GNT, 256>>>(GI + (size_t)t * Bb * H3, hp, Whh, bhh,
                                    HS + (size_t)t * Bb * Hh);
    }

    // out_s = relu(HS @ W3^T + b3), rows in (t*B+b) order
    sgemm_tn<<<dim3(Pp / BN, MT / BM), 256>>>(HS, W3, b3, S, MT, Pp, Hh, 1, 0);

    // primary heads + h_last
    head_kernel<<<6144, 256>>>(S, Wp, bp, label, out);
    copy_hlast<<<(Bb * Hh + 255) / 256, 256>>>(HS + (size_t)(Tt - 1) * Bb * Hh,
                                               out + Bb * Tt * 3);
}